// round 10
// baseline (speedup 1.0000x reference)
#include <cuda_runtime.h>
#include <cuda_fp16.h>
#include <cstdint>
#include <math.h>

// ---------------------------------------------------------------- constants
#define RR 8
#define NN 128
#define DD 512
#define HH 256
#define KTOP 64
#define NCAND 128
#define NPAIR (NN*NN)          // 16384
#define KC 64                  // K per chunk (64 fp16 = 128B rows, SW128 atom)
#define NCH 8                  // 512 / 64
#define STG 81920              // bytes per smem stage (A + B_hi + B_lo)
#define OFF_A   0              // 16384 B  (128 rows x 128B)
#define OFF_BHI 16384          // 32768 B  (256 rows x 128B)
#define OFF_BLO 49152          // 32768 B
#define SWZ(o) ((o) ^ (((o) >> 3) & 0x70))

// ---------------------------------------------------------------- scratch
__device__ float g_pf[KTOP * DD];                 // gathered mean pair feats
__device__ int   g_topk[KTOP];
__device__ int   g_cand[NCAND];
__device__ float g_cand_logit[NCAND];
__device__ __align__(16) __half g_whi[2][NCH * 16384]; // W split hi (fp16)
__device__ __align__(16) __half g_wlo[2][NCH * 16384]; // W split lo (fp16)

// ---------------------------------------------------------------- helpers
static __device__ __forceinline__ uint32_t smem_u32(const void* p) {
    uint32_t a;
    asm("{ .reg .u64 t; cvta.to.shared.u64 t, %1; cvt.u32.u64 %0, t; }"
        : "=r"(a) : "l"(p));
    return a;
}
static __device__ __forceinline__ void ldsm4(uint32_t* r, uint32_t addr) {
    asm volatile("ldmatrix.sync.aligned.m8n8.x4.shared.b16 {%0,%1,%2,%3}, [%4];"
                 : "=r"(r[0]), "=r"(r[1]), "=r"(r[2]), "=r"(r[3]) : "r"(addr));
}
static __device__ __forceinline__ void mma16816(float* d, const uint32_t* a,
                                                uint32_t b0, uint32_t b1) {
    asm volatile(
        "mma.sync.aligned.m16n8k16.row.col.f32.f16.f16.f32 "
        "{%0,%1,%2,%3}, {%4,%5,%6,%7}, {%8,%9}, {%0,%1,%2,%3};"
        : "+f"(d[0]), "+f"(d[1]), "+f"(d[2]), "+f"(d[3])
        : "r"(a[0]), "r"(a[1]), "r"(a[2]), "r"(a[3]), "r"(b0), "r"(b1));
}
#define CP_ASYNC16(dst, src) \
    asm volatile("cp.async.cg.shared.global [%0], [%1], 16;" \
                 :: "r"(dst), "l"(src) : "memory")
#define CP_COMMIT() asm volatile("cp.async.commit_group;" ::: "memory")
#define CP_WAIT0()  asm volatile("cp.async.wait_group 0;" ::: "memory")
#define CP_WAIT1()  asm volatile("cp.async.wait_group 1;" ::: "memory")

static __device__ __forceinline__ uint32_t pkh(float a, float b) {
    __half2 h2 = __floats2half2_rn(a, b);
    return *reinterpret_cast<uint32_t*>(&h2);
}

// ---------------------------------------------------------------- W prep
__global__ void prep_w_kernel(const float* __restrict__ w1a,
                              const float* __restrict__ w1b) {
    int idx = blockIdx.x * 256 + threadIdx.x;      // 0..262143
    int arr = idx >> 17;
    int rem = idx & 131071;
    int c  = rem >> 14;
    int n  = (rem >> 6) & 255;
    int kk = rem & 63;
    const float* w = arr ? w1b : w1a;
    float f = w[(size_t)(c * 64 + kk) * HH + n];
    __half hi = __float2half_rn(f);
    __half lo = __float2half_rn(f - __half2float(hi));
    uint32_t off = (uint32_t)c * 32768u + SWZ((uint32_t)(n * 128 + kk * 2));
    *(__half*)((char*)g_whi[arr] + off) = hi;
    *(__half*)((char*)g_wlo[arr] + off) = lo;
}

// ---------------------------------------------------------------- fused GEMM
// 512 threads, 16 warps: warp grid 4(M) x 4(N), warp tile 32x64.
// acc = x_fp16 * (wh + wl)   (W exactly split in fp16; only x rounded once)
template <int PHASE>
__global__ __launch_bounds__(512, 1)
void gemm_mlp_kernel(const float* __restrict__ obj, const float* __restrict__ geo,
                     const float* __restrict__ b1, const float* __restrict__ w2,
                     const float* __restrict__ b2, float* __restrict__ outv) {
    extern __shared__ char smraw[];
    char* sm = (char*)(((uintptr_t)smraw + 1023) & ~(uintptr_t)1023);
    __shared__ float s_b1[HH], s_w2[HH];
    __shared__ float red[128][5];
    __shared__ float rowlogit[128];

    const int t = threadIdx.x;
    const int wid = t >> 5, lane = t & 31;
    const int wm = wid >> 2;           // 0..3  (M warp)
    const int wn = wid & 3;            // 0..3  (N warp)
    const uint32_t smb = smem_u32(sm);

    if (t < HH) { s_b1[t] = b1[t]; s_w2[t] = w2[t]; }

    const char* wsrcH = (const char*)g_whi[PHASE];
    const char* wsrcL = (const char*)g_wlo[PHASE];

    const int rsub = t >> 4;          // 0..31
    const int f4   = t & 15;

    float acc[2][8][4];
#pragma unroll
    for (int a = 0; a < 2; a++)
#pragma unroll
        for (int b = 0; b < 8; b++)
#pragma unroll
            for (int cq = 0; cq < 4; cq++) acc[a][b][cq] = 0.f;

    uint2 xp[4];
    auto buildX = [&](int c) {
#pragma unroll
        for (int m = 0; m < 4; m++) {
            const int row = m * 32 + rsub;
            float4 x;
            if (PHASE == 0) {
                int pl = row >> 3, r = row & 7;
                int p = blockIdx.x * 16 + pl;
                int i = p >> 7, j = p & 127;
                const float4 a = *(const float4*)(obj + (size_t)(r * NN + i) * DD
                                                  + c * KC + f4 * 4);
                const float4 b = *(const float4*)(obj + (size_t)(r * NN + j) * DD
                                                  + c * KC + f4 * 4);
                const float4 g4 = *(const float4*)(geo
                    + (size_t)((r * NN + i) * NN + j) * DD + c * KC + f4 * 4);
                x.x = fmaf(a.x, b.x, g4.x);
                x.y = fmaf(a.y, b.y, g4.y);
                x.z = fmaf(a.z, b.z, g4.z);
                x.w = fmaf(a.w, b.w, g4.w);
            } else {
                int g = blockIdx.x * 128 + row;
                const float4 a = *(const float4*)(g_pf + (g >> 6) * DD
                                                  + c * KC + f4 * 4);
                const float4 b = *(const float4*)(g_pf + (g & 63) * DD
                                                  + c * KC + f4 * 4);
                x.x = a.x * b.x; x.y = a.y * b.y;
                x.z = a.z * b.z; x.w = a.w * b.w;
            }
            xp[m].x = pkh(x.x, x.y);
            xp[m].y = pkh(x.z, x.w);
        }
    };
    auto stageStore = [&](char* bs, uint32_t bsb, int c) {
#pragma unroll
        for (int m = 0; m < 4; m++) {
            const uint32_t boff = SWZ((uint32_t)((m * 32 + rsub) * 128 + f4 * 8));
            *(uint2*)(bs + OFF_A + boff) = xp[m];
        }
        const char* sH = wsrcH + c * 32768;
        const char* sL = wsrcL + c * 32768;
#pragma unroll
        for (int m = 0; m < 4; m++) {
            uint32_t o = (uint32_t)(m * 8192 + t * 16);
            CP_ASYNC16(bsb + OFF_BHI + o, sH + o);
            CP_ASYNC16(bsb + OFF_BLO + o, sL + o);
        }
        CP_COMMIT();
    };

    const uint32_t aRow = (uint32_t)(wm * 32 + (lane & 15));
    const uint32_t nRow = (uint32_t)(wn * 64 + (lane & 15));
    const uint32_t kbL  = (uint32_t)((lane >> 4) * 16);

    buildX(0);
    stageStore(sm, smb, 0);
    buildX(1);

#pragma unroll 1
    for (int c = 0; c < NCH; c++) {
        const int st = c & 1;
        const uint32_t sbb = smb + st * STG;
        if (c + 1 < NCH) {
            stageStore(sm + (st ^ 1) * STG, smb + (st ^ 1) * STG, c + 1);
            CP_WAIT1();
        } else {
            CP_WAIT0();
        }
        __syncthreads();
        const uint32_t sA = sbb + OFF_A;
        const uint32_t sBhi = sbb + OFF_BHI, sBlo = sbb + OFF_BLO;
#pragma unroll
        for (int ks = 0; ks < 4; ks++) {
            const uint32_t kbase = ks * 32 + kbL;
            uint32_t ah[2][4];
#pragma unroll
            for (int mt = 0; mt < 2; mt++) {
                uint32_t off = SWZ((aRow + mt * 16) * 128 + kbase);
                ldsm4(ah[mt], sA + off);
            }
#pragma unroll
            for (int nh = 0; nh < 2; nh++) {
                uint32_t bh[2][4], bl[2][4];
#pragma unroll
                for (int p = 0; p < 2; p++) {
                    uint32_t off = SWZ((nRow + nh * 32 + p * 16) * 128 + kbase);
                    ldsm4(bh[p], sBhi + off);
                    ldsm4(bl[p], sBlo + off);
                }
#pragma unroll
                for (int mt = 0; mt < 2; mt++)
#pragma unroll
                    for (int p = 0; p < 2; p++)
#pragma unroll
                        for (int e = 0; e < 2; e++) {
                            float* d = acc[mt][nh * 4 + p * 2 + e];
                            mma16816(d, ah[mt], bh[p][e], bh[p][e + 2]);
                            mma16816(d, ah[mt], bl[p][e], bl[p][e + 2]);
                        }
            }
        }
        if (c + 2 < NCH) buildX(c + 2);
        __syncthreads();
    }

    // ---- epilogue: bias, relu, dot w2 ----
#pragma unroll
    for (int mt = 0; mt < 2; mt++) {
        float ps0 = 0.f, ps1 = 0.f;
#pragma unroll
        for (int nt = 0; nt < 8; nt++) {
            int h = wn * 64 + nt * 8 + (lane & 3) * 2;
            float b0 = s_b1[h],  w0 = s_w2[h];
            float b1v = s_b1[h + 1], w1v = s_w2[h + 1];
            ps0 = fmaf(fmaxf(acc[mt][nt][0] + b0, 0.f),  w0,  ps0);
            ps0 = fmaf(fmaxf(acc[mt][nt][1] + b1v, 0.f), w1v, ps0);
            ps1 = fmaf(fmaxf(acc[mt][nt][2] + b0, 0.f),  w0,  ps1);
            ps1 = fmaf(fmaxf(acc[mt][nt][3] + b1v, 0.f), w1v, ps1);
        }
        ps0 += __shfl_xor_sync(0xffffffffu, ps0, 1);
        ps0 += __shfl_xor_sync(0xffffffffu, ps0, 2);
        ps1 += __shfl_xor_sync(0xffffffffu, ps1, 1);
        ps1 += __shfl_xor_sync(0xffffffffu, ps1, 2);
        if ((lane & 3) == 0) {
            int r0 = wm * 32 + mt * 16 + (lane >> 2);
            red[r0][wn] = ps0;
            red[r0 + 8][wn] = ps1;
        }
    }
    __syncthreads();
    if (t < 128) rowlogit[t] = red[t][0] + red[t][1] + red[t][2] + red[t][3];
    __syncthreads();
    if (PHASE == 0) {
        if (t < 16) {
            float s = 0.f;
#pragma unroll
            for (int r = 0; r < 8; r++) s += rowlogit[t * 8 + r];
            outv[blockIdx.x * 16 + t] = s * 0.125f + b2[0];
        }
    } else {
        if (t < 128) outv[blockIdx.x * 128 + t] = rowlogit[t] + b2[0];
    }
}

// ---------------------------------------------------------------- candidates
// top-NCAND by approximate logit (value desc, index asc); masked -> -inf.
__global__ __launch_bounds__(1024) void cand_kernel(const float* __restrict__ logits,
                                                    const float* __restrict__ mask) {
    const int t = threadIdx.x;
    const int wid = t >> 5, lane = t & 31;
    float v[16];
#pragma unroll
    for (int u = 0; u < 16; u++) {
        int p = u * 1024 + t;
        v[u] = (mask[p] != 0.f) ? logits[p] : -3.4e38f;
    }
    float lmax = -3.4e38f; int ls = 0;
#pragma unroll
    for (int u = 0; u < 16; u++) if (v[u] > lmax) { lmax = v[u]; ls = u; }

    __shared__ float wv[32];
    __shared__ int wi2[32];
    __shared__ int s_best;
    for (int sel = 0; sel < NCAND; sel++) {
        float bv = lmax;
        int bi = ls * 1024 + t;
#pragma unroll
        for (int o = 16; o > 0; o >>= 1) {
            float ov = __shfl_down_sync(0xffffffffu, bv, o);
            int oi = __shfl_down_sync(0xffffffffu, bi, o);
            if (ov > bv || (ov == bv && oi < bi)) { bv = ov; bi = oi; }
        }
        if (lane == 0) { wv[wid] = bv; wi2[wid] = bi; }
        __syncthreads();
        if (wid == 0) {
            bv = wv[lane]; bi = wi2[lane];
#pragma unroll
            for (int o = 16; o > 0; o >>= 1) {
                float ov = __shfl_down_sync(0xffffffffu, bv, o);
                int oi = __shfl_down_sync(0xffffffffu, bi, o);
                if (ov > bv || (ov == bv && oi < bi)) { bv = ov; bi = oi; }
            }
            if (lane == 0) { g_cand[sel] = bi; s_best = bi; }
        }
        __syncthreads();
        int w = s_best;
        if ((w & 1023) == t) {
            v[w >> 10] = -3.4e38f;
            lmax = -3.4e38f; ls = 0;
#pragma unroll
            for (int u = 0; u < 16; u++) if (v[u] > lmax) { lmax = v[u]; ls = u; }
        }
    }
}

// ---------------------------------------------------------------- refine
// Exact fp32 r-mean logit for each candidate pair. 1 block per candidate.
__global__ __launch_bounds__(256) void refine_kernel(const float* __restrict__ obj,
                                                     const float* __restrict__ geo,
                                                     const float* __restrict__ w1,
                                                     const float* __restrict__ b1,
                                                     const float* __restrict__ w2,
                                                     const float* __restrict__ b2) {
    __shared__ float xs[RR][DD];
    __shared__ float rsum[8][RR];
    __shared__ float rtot[RR];
    const int ci = blockIdx.x;
    const int ind = g_cand[ci];
    const int i = ind >> 7, j = ind & 127;
    const int t = threadIdx.x;
    const int wid = t >> 5, lane = t & 31;

#pragma unroll
    for (int r = 0; r < RR; r++)
        for (int d = t; d < DD; d += 256)
            xs[r][d] = fmaf(obj[(size_t)(r * NN + i) * DD + d],
                            obj[(size_t)(r * NN + j) * DD + d],
                            geo[(size_t)((r * NN + i) * NN + j) * DD + d]);
    __syncthreads();

    float z[RR];
#pragma unroll
    for (int r = 0; r < RR; r++) z[r] = 0.f;
    const int h = t;
#pragma unroll 4
    for (int d = 0; d < DD; d++) {
        float w = w1[(size_t)d * HH + h];
#pragma unroll
        for (int r = 0; r < RR; r++) z[r] = fmaf(xs[r][d], w, z[r]);
    }
    const float bb = b1[h], ww = w2[h];
#pragma unroll
    for (int r = 0; r < RR; r++) {
        float v = fmaxf(z[r] + bb, 0.f) * ww;
#pragma unroll
        for (int o = 16; o > 0; o >>= 1) v += __shfl_xor_sync(0xffffffffu, v, o);
        if (lane == 0) rsum[wid][r] = v;
    }
    __syncthreads();
    if (t < RR) {
        float s = 0.f;
#pragma unroll
        for (int w = 0; w < 8; w++) s += rsum[w][t];
        rtot[t] = s;
    }
    __syncthreads();
    if (t == 0) {
        float s = 0.f;
#pragma unroll
        for (int r = 0; r < RR; r++) s += rtot[r];
        g_cand_logit[ci] = s * 0.125f + b2[0];
    }
}

// ---------------------------------------------------------------- final top-64
__global__ __launch_bounds__(NCAND) void final_topk_kernel(float* __restrict__ out_inds) {
    const int t = threadIdx.x;
    const int wid = t >> 5, lane = t & 31;
    float v = g_cand_logit[t];
    int idx = g_cand[t];
    __shared__ float wv[4];
    __shared__ int wi2[4];
    __shared__ int s_best;
    for (int sel = 0; sel < KTOP; sel++) {
        float bv = v; int bi = idx;
#pragma unroll
        for (int o = 16; o > 0; o >>= 1) {
            float ov = __shfl_down_sync(0xffffffffu, bv, o);
            int oi = __shfl_down_sync(0xffffffffu, bi, o);
            if (ov > bv || (ov == bv && oi < bi)) { bv = ov; bi = oi; }
        }
        if (lane == 0) { wv[wid] = bv; wi2[wid] = bi; }
        __syncthreads();
        if (t == 0) {
            bv = wv[0]; bi = wi2[0];
#pragma unroll
            for (int w = 1; w < 4; w++)
                if (wv[w] > bv || (wv[w] == bv && wi2[w] < bi)) { bv = wv[w]; bi = wi2[w]; }
            g_topk[sel] = bi;
            out_inds[sel] = (float)bi;
            s_best = bi;
        }
        __syncthreads();
        if (idx == s_best) v = -3.4e38f;
    }
}

// ---------------------------------------------------------------- gather
__global__ void gather_pf_kernel(const float* __restrict__ obj,
                                 const float* __restrict__ geo) {
    const int b = blockIdx.x;
    const int ind = g_topk[b];
    const int i = ind >> 7, j = ind & 127;
    const int d = threadIdx.x * 4;
    float4 a = make_float4(0.f, 0.f, 0.f, 0.f);
#pragma unroll
    for (int r = 0; r < RR; r++) {
        const float4 oi = *(const float4*)&obj[(size_t)(r * NN + i) * DD + d];
        const float4 oj = *(const float4*)&obj[(size_t)(r * NN + j) * DD + d];
        const float4 g4 = *(const float4*)&geo[(size_t)((r * NN + i) * NN + j) * DD + d];
        a.x += fmaf(oi.x, oj.x, g4.x);
        a.y += fmaf(oi.y, oj.y, g4.y);
        a.z += fmaf(oi.z, oj.z, g4.z);
        a.w += fmaf(oi.w, oj.w, g4.w);
    }
    a.x *= (1.f / RR); a.y *= (1.f / RR); a.z *= (1.f / RR); a.w *= (1.f / RR);
    *(float4*)&g_pf[b * DD + d] = a;
}

// ---------------------------------------------------------------- launch
extern "C" void kernel_launch(void* const* d_in, const int* in_sizes, int n_in,
                              void* d_out, int out_size) {
    const float* obj  = (const float*)d_in[0];
    const float* geo  = (const float*)d_in[1];
    const float* mask = (const float*)d_in[2];
    const float* w1a  = (const float*)d_in[3];
    const float* b1a  = (const float*)d_in[4];
    const float* w2a  = (const float*)d_in[5];
    const float* b2a  = (const float*)d_in[6];
    const float* w1b  = (const float*)d_in[7];
    const float* b1b  = (const float*)d_in[8];
    const float* w2b  = (const float*)d_in[9];
    const float* b2b  = (const float*)d_in[10];
    float* out = (float*)d_out;

    const int dyn = 2 * STG + 1024;  // +1024 for manual alignment
    cudaFuncSetAttribute(gemm_mlp_kernel<0>,
                         cudaFuncAttributeMaxDynamicSharedMemorySize, dyn);
    cudaFuncSetAttribute(gemm_mlp_kernel<1>,
                         cudaFuncAttributeMaxDynamicSharedMemorySize, dyn);

    prep_w_kernel<<<1024, 256>>>(w1a, w1b);
    gemm_mlp_kernel<0><<<NPAIR / 16, 512, dyn>>>(obj, geo, b1a, w2a, b2a, out);
    cand_kernel<<<1, 1024>>>(out, mask);
    refine_kernel<<<NCAND, 256>>>(obj, geo, w1a, b1a, w2a, b2a);
    final_topk_kernel<<<1, NCAND>>>(out + NPAIR + KTOP * KTOP);
    gather_pf_kernel<<<KTOP, 128>>>(obj, geo);
    gemm_mlp_kernel<1><<<KTOP * KTOP / 128, 512, dyn>>>(obj, geo, b1b, w2b, b2b,
                                                        out + NPAIR);
}